// round 10
// baseline (speedup 1.0000x reference)
#include <cuda_runtime.h>

// out[i, j] = (2*x[i, j] + 3) / (i + 1), x is 8192x8192 fp32.
// HBM-bound streaming, ~91% of 8TB/s spec. R10: Blackwell 256-bit global
// ld/st (ld.global.v8.f32 -> LDG.256) — halves LSU instruction count and
// L1tex wavefront count vs float4 at the same 8KB/CTA batch (R7 U-curve
// optimum: 128T x 64B/thread). Front-batched loads, streaming (.cs) hints,
// 32-bit indexing.

static constexpr int N_ROWS = 8192;
static constexpr int N_COLS = 8192;
static constexpr int N_V8 = N_ROWS * (N_COLS / 8);      // 2^23 chunks of 8 floats
static constexpr int THREADS = 128;
static constexpr int UNROLL = 2;                        // 2 x 32B = 64B/thread
// 2^23 / (128*2) = 32768 blocks, exact — no tail.
static constexpr int BLOCKS = N_V8 / (THREADS * UNROLL);

struct __align__(32) f8 { float v[8]; };

__device__ __forceinline__ f8 ldg256_cs(const f8* p) {
    f8 r;
    asm volatile("ld.global.cs.v8.f32 {%0,%1,%2,%3,%4,%5,%6,%7}, [%8];"
                 : "=f"(r.v[0]), "=f"(r.v[1]), "=f"(r.v[2]), "=f"(r.v[3]),
                   "=f"(r.v[4]), "=f"(r.v[5]), "=f"(r.v[6]), "=f"(r.v[7])
                 : "l"(p));
    return r;
}

__device__ __forceinline__ void stg256_cs(f8* p, const f8& r) {
    asm volatile("st.global.cs.v8.f32 [%0], {%1,%2,%3,%4,%5,%6,%7,%8};"
                 :: "l"(p),
                    "f"(r.v[0]), "f"(r.v[1]), "f"(r.v[2]), "f"(r.v[3]),
                    "f"(r.v[4]), "f"(r.v[5]), "f"(r.v[6]), "f"(r.v[7])
                 : "memory");
}

__global__ void __launch_bounds__(THREADS)
affine_rowdiv_kernel(const f8* __restrict__ in, f8* __restrict__ out) {
    int base = blockIdx.x * (THREADS * UNROLL) + threadIdx.x;

    // Front-batch 2 independent LDG.256 per thread (64B in flight).
    f8 v[UNROLL];
#pragma unroll
    for (int k = 0; k < UNROLL; k++) {
        v[k] = ldg256_cs(&in[base + k * THREADS]);
    }

#pragma unroll
    for (int k = 0; k < UNROLL; k++) {
        int idx = base + k * THREADS;
        // 1024 v8-chunks per row -> row = idx >> 10 (8192 % 8 == 0: same row)
        int row = idx >> 10;
        float inv = 1.0f / (float)(row + 1);
        f8 r;
#pragma unroll
        for (int e = 0; e < 8; e++) {
            r.v[e] = fmaf(2.0f, v[k].v[e], 3.0f) * inv;
        }
        stg256_cs(&out[idx], r);
    }
}

extern "C" void kernel_launch(void* const* d_in, const int* in_sizes, int n_in,
                              void* d_out, int out_size) {
    const f8* in = (const f8*)d_in[0];
    f8* out = (f8*)d_out;
    affine_rowdiv_kernel<<<BLOCKS, THREADS>>>(in, out);
}

// round 11
// speedup vs baseline: 1.0047x; 1.0047x over previous
#include <cuda_runtime.h>

// out[i, j] = (2*x[i, j] + 3) / (i + 1), x is 8192x8192 fp32.
// FINAL (R7 config): HBM-bound streaming at ~7.3 TB/s effective (~91% of
// 8 TB/s HBM3e spec) — measured roofline for a zero-reuse 512 MiB stream.
//
// Sweep results (ncu dur): block 64/128/256/512T -> 75.4/73.4/74.3/78.7 us
// (U-curve min at 128T = 512 vecs/CTA); MLP 1/4/8 -> 80.2/74.3/74.2;
// persistent grid -> 85.8 (load-imbalance tail); LDG.256 -> 74.8 (neutral);
// 64-bit idx, occupancy 48-82% -> all neutral. DRAM bus is the binding
// resource; no kernel-structure lever moves it further.
//
// THREADS=128, UNROLL=4, flat 32768-CTA grid (exact, no tail),
// front-batched LDG.128 (4 in flight/thread), streaming (.cs) hints,
// 32-bit indexing. One MUFU.RCP per float4 (row-uniform divisor).

static constexpr int N_ROWS = 8192;
static constexpr int N_COLS = 8192;
static constexpr int N_VEC = (N_ROWS / 4) * N_COLS;     // 2^24 float4s (fits int)
static constexpr int THREADS = 128;
static constexpr int UNROLL = 4;
// 2^24 / (128*4) = 32768 blocks, exact — no tail.
static constexpr int BLOCKS = N_VEC / (THREADS * UNROLL);

__global__ void __launch_bounds__(THREADS)
affine_rowdiv_kernel(const float4* __restrict__ in, float4* __restrict__ out) {
    int base = blockIdx.x * (THREADS * UNROLL) + threadIdx.x;

    // Front-batch 4 independent LDG.128 per thread.
    float4 v[UNROLL];
#pragma unroll
    for (int k = 0; k < UNROLL; k++) {
        v[k] = __ldcs(&in[base + k * THREADS]);
    }

#pragma unroll
    for (int k = 0; k < UNROLL; k++) {
        int idx = base + k * THREADS;
        // 2048 float4s per row -> row = idx >> 11 (8192 % 4 == 0: same row)
        int row = idx >> 11;
        float inv = 1.0f / (float)(row + 1);
        float4 r;
        r.x = fmaf(2.0f, v[k].x, 3.0f) * inv;
        r.y = fmaf(2.0f, v[k].y, 3.0f) * inv;
        r.z = fmaf(2.0f, v[k].z, 3.0f) * inv;
        r.w = fmaf(2.0f, v[k].w, 3.0f) * inv;
        __stcs(&out[idx], r);
    }
}

extern "C" void kernel_launch(void* const* d_in, const int* in_sizes, int n_in,
                              void* d_out, int out_size) {
    const float4* in = (const float4*)d_in[0];
    float4* out = (float4*)d_out;
    affine_rowdiv_kernel<<<BLOCKS, THREADS>>>(in, out);
}

// round 12
// speedup vs baseline: 1.0051x; 1.0004x over previous
#include <cuda_runtime.h>

// out[i, j] = (2*x[i, j] + 3) / (i + 1), x is 8192x8192 fp32.
// HBM-bound streaming at ~7.2 TB/s effective (~90% of 8 TB/s HBM3e spec).
// R12: last unmeasured cell of the (batch x shape) matrix — 512 vecs/CTA
// (the U-curve minimum) realized as 256T x UNROLL=2 instead of 128T x U4:
// same per-CTA L1tex batch, more warps/CTA, lower regs -> higher occupancy.
// Flat 32768-CTA grid (exact), front-batched LDG.128, streaming hints,
// 32-bit indexing, one MUFU.RCP per float4.

static constexpr int N_ROWS = 8192;
static constexpr int N_COLS = 8192;
static constexpr int N_VEC = (N_ROWS / 4) * N_COLS;     // 2^24 float4s (fits int)
static constexpr int THREADS = 256;
static constexpr int UNROLL = 2;
// 2^24 / (256*2) = 32768 blocks, exact — no tail.
static constexpr int BLOCKS = N_VEC / (THREADS * UNROLL);

__global__ void __launch_bounds__(THREADS)
affine_rowdiv_kernel(const float4* __restrict__ in, float4* __restrict__ out) {
    int base = blockIdx.x * (THREADS * UNROLL) + threadIdx.x;

    // Front-batch 2 independent LDG.128 per thread.
    float4 v[UNROLL];
#pragma unroll
    for (int k = 0; k < UNROLL; k++) {
        v[k] = __ldcs(&in[base + k * THREADS]);
    }

#pragma unroll
    for (int k = 0; k < UNROLL; k++) {
        int idx = base + k * THREADS;
        // 2048 float4s per row -> row = idx >> 11 (8192 % 4 == 0: same row)
        int row = idx >> 11;
        float inv = 1.0f / (float)(row + 1);
        float4 r;
        r.x = fmaf(2.0f, v[k].x, 3.0f) * inv;
        r.y = fmaf(2.0f, v[k].y, 3.0f) * inv;
        r.z = fmaf(2.0f, v[k].z, 3.0f) * inv;
        r.w = fmaf(2.0f, v[k].w, 3.0f) * inv;
        __stcs(&out[idx], r);
    }
}

extern "C" void kernel_launch(void* const* d_in, const int* in_sizes, int n_in,
                              void* d_out, int out_size) {
    const float4* in = (const float4*)d_in[0];
    float4* out = (float4*)d_out;
    affine_rowdiv_kernel<<<BLOCKS, THREADS>>>(in, out);
}